// round 1
// baseline (speedup 1.0000x reference)
#include <cuda_runtime.h>
#include <cstdint>

#define NN 50000
#define NE 800000
#define DD 128
#define BN_EPS 1e-5f

// ---------------- scratch (no allocations allowed) ----------------
__device__ __align__(256) float g_deg[NN];
__device__ __align__(256) float g_norm[NN];
__device__ __align__(256) float g_agg[(size_t)NN * DD];
__device__ __align__(256) float g_h[(size_t)NN * DD];
__device__ __align__(256) float g_Wt[DD * DD];      // Wt[k][j] = W[j][k]
__device__ __align__(16)  float g_colsum[DD];
__device__ __align__(16)  float g_colsumsq[DD];
__device__ __align__(16)  float g_scale[DD];
__device__ __align__(16)  float g_shift[DD];

// ---------------- kernels ----------------

// zero deg, agg, col stats
__global__ void k_init() {
    int t = blockIdx.x * 256 + threadIdx.x;
    const int total4 = NN * DD / 4;
    if (t < total4)
        reinterpret_cast<float4*>(g_agg)[t] = make_float4(0.f, 0.f, 0.f, 0.f);
    if (t < NN) g_deg[t] = 0.f;
    if (t < DD) { g_colsum[t] = 0.f; g_colsumsq[t] = 0.f; }
}

__global__ void k_deg(const int* __restrict__ dst) {
    int e = blockIdx.x * 256 + threadIdx.x;
    if (e < NE) atomicAdd(&g_deg[dst[e]], 1.0f);
}

// norm = clip(deg,1)^-0.5  and  Wt = W^T
__global__ void k_prep(const float* __restrict__ W) {
    int t = blockIdx.x * 256 + threadIdx.x;
    if (t < NN) g_norm[t] = rsqrtf(fmaxf(g_deg[t], 1.0f));
    if (t < DD * DD) {
        int k = t & (DD - 1);
        int j = t >> 7;
        g_Wt[k * DD + j] = W[j * DD + k];
    }
}

// one edge per 8-lane group; each lane moves 4 float4s (MLP=4)
__global__ void __launch_bounds__(256) k_scatter(const float* __restrict__ feat,
                                                 const int* __restrict__ src,
                                                 const int* __restrict__ dst) {
    int gid = blockIdx.x * 256 + threadIdx.x;
    int e = gid >> 3;
    if (e >= NE) return;
    int l = gid & 7;
    int s = __ldg(src + e);
    int d = __ldg(dst + e);
    float ns = g_norm[s];
    const float4* f4 = reinterpret_cast<const float4*>(feat) + (size_t)s * (DD / 4);
    float* outp = g_agg + (size_t)d * DD;

    float4 v0 = f4[l];
    float4 v1 = f4[l + 8];
    float4 v2 = f4[l + 16];
    float4 v3 = f4[l + 24];
    v0.x *= ns; v0.y *= ns; v0.z *= ns; v0.w *= ns;
    v1.x *= ns; v1.y *= ns; v1.z *= ns; v1.w *= ns;
    v2.x *= ns; v2.y *= ns; v2.z *= ns; v2.w *= ns;
    v3.x *= ns; v3.y *= ns; v3.z *= ns; v3.w *= ns;

    asm volatile("red.global.add.v4.f32 [%0], {%1,%2,%3,%4};" ::
                 "l"(outp + (l + 0)  * 4), "f"(v0.x), "f"(v0.y), "f"(v0.z), "f"(v0.w) : "memory");
    asm volatile("red.global.add.v4.f32 [%0], {%1,%2,%3,%4};" ::
                 "l"(outp + (l + 8)  * 4), "f"(v1.x), "f"(v1.y), "f"(v1.z), "f"(v1.w) : "memory");
    asm volatile("red.global.add.v4.f32 [%0], {%1,%2,%3,%4};" ::
                 "l"(outp + (l + 16) * 4), "f"(v2.x), "f"(v2.y), "f"(v2.z), "f"(v2.w) : "memory");
    asm volatile("red.global.add.v4.f32 [%0], {%1,%2,%3,%4};" ::
                 "l"(outp + (l + 24) * 4), "f"(v3.x), "f"(v3.y), "f"(v3.z), "f"(v3.w) : "memory");
}

// h = (agg @ W^T + b) * norm[row]; fused BN column stats
// block = 256 threads, 32 rows; thread (tx,ty): 4 rows x 4 cols register tile
__global__ void __launch_bounds__(256) k_gemm(const float* __restrict__ bias) {
    __shared__ float As[32][DD];        // 16 KB
    __shared__ float s_sum[8][DD];      // 4 KB
    __shared__ float s_ss[8][DD];       // 4 KB

    int tid = threadIdx.x;
    int tx = tid & 31, ty = tid >> 5;
    int row0 = blockIdx.x * 32;

    const float4 zero4 = make_float4(0.f, 0.f, 0.f, 0.f);
    const float4* aggp = reinterpret_cast<const float4*>(g_agg) + (size_t)row0 * (DD / 4);
    float4* As4 = reinterpret_cast<float4*>(&As[0][0]);
#pragma unroll
    for (int i = 0; i < 4; i++) {
        int idx = tid + i * 256;            // 0..1023 float4s
        int r = idx >> 5;                   // local row
        As4[idx] = (row0 + r < NN) ? aggp[idx] : zero4;
    }
    __syncthreads();

    int c0 = tx * 4;
    float acc[4][4] = {};
    const float* wt = g_Wt + c0;
#pragma unroll 4
    for (int k = 0; k < DD; k++) {
        float4 w = *reinterpret_cast<const float4*>(wt + k * DD);  // L1-resident
#pragma unroll
        for (int r = 0; r < 4; r++) {
            float a = As[ty * 4 + r][k];    // broadcast, conflict-free
            acc[r][0] += a * w.x;
            acc[r][1] += a * w.y;
            acc[r][2] += a * w.z;
            acc[r][3] += a * w.w;
        }
    }

    float4 bb = *reinterpret_cast<const float4*>(bias + c0);
    float sum[4] = {0.f, 0.f, 0.f, 0.f};
    float ss[4]  = {0.f, 0.f, 0.f, 0.f};
#pragma unroll
    for (int r = 0; r < 4; r++) {
        int rg = row0 + ty * 4 + r;
        if (rg < NN) {
            float nr = g_norm[rg];
            float4 h;
            h.x = (acc[r][0] + bb.x) * nr;
            h.y = (acc[r][1] + bb.y) * nr;
            h.z = (acc[r][2] + bb.z) * nr;
            h.w = (acc[r][3] + bb.w) * nr;
            *reinterpret_cast<float4*>(g_h + (size_t)rg * DD + c0) = h;
            sum[0] += h.x; ss[0] += h.x * h.x;
            sum[1] += h.y; ss[1] += h.y * h.y;
            sum[2] += h.z; ss[2] += h.z * h.z;
            sum[3] += h.w; ss[3] += h.w * h.w;
        }
    }
#pragma unroll
    for (int i = 0; i < 4; i++) {
        s_sum[ty][c0 + i] = sum[i];
        s_ss[ty][c0 + i]  = ss[i];
    }
    __syncthreads();
    if (tid < DD) {
        float S = 0.f, Q = 0.f;
#pragma unroll
        for (int j = 0; j < 8; j++) { S += s_sum[j][tid]; Q += s_ss[j][tid]; }
        atomicAdd(&g_colsum[tid], S);
        atomicAdd(&g_colsumsq[tid], Q);
    }
}

__global__ void k_finalize(const float* __restrict__ gamma, const float* __restrict__ beta) {
    int c = threadIdx.x;
    if (c < DD) {
        const float invN = 1.0f / (float)NN;
        float mean = g_colsum[c] * invN;
        float var  = g_colsumsq[c] * invN - mean * mean;
        float inv  = rsqrtf(var + BN_EPS);
        float sc   = gamma[c] * inv;
        g_scale[c] = sc;
        g_shift[c] = beta[c] - mean * sc;
    }
}

__global__ void k_epilogue(const float* __restrict__ feat, float* __restrict__ out) {
    int t = blockIdx.x * 256 + threadIdx.x;
    const int total4 = NN * DD / 4;
    if (t >= total4) return;
    int cq = t & 31;
    float4 sc = reinterpret_cast<const float4*>(g_scale)[cq];
    float4 sh = reinterpret_cast<const float4*>(g_shift)[cq];
    float4 h  = reinterpret_cast<const float4*>(g_h)[t];
    float4 f  = reinterpret_cast<const float4*>(feat)[t];
    float4 o;
    o.x = f.x + fmaxf(h.x * sc.x + sh.x, 0.f);
    o.y = f.y + fmaxf(h.y * sc.y + sh.y, 0.f);
    o.z = f.z + fmaxf(h.z * sc.z + sh.z, 0.f);
    o.w = f.w + fmaxf(h.w * sc.w + sh.w, 0.f);
    reinterpret_cast<float4*>(out)[t] = o;
}

// ---------------- launch ----------------
extern "C" void kernel_launch(void* const* d_in, const int* in_sizes, int n_in,
                              void* d_out, int out_size) {
    const float* feat  = (const float*)d_in[0];
    const float* W     = (const float*)d_in[1];
    const float* b     = (const float*)d_in[2];
    const float* gamma = (const float*)d_in[3];
    const float* beta  = (const float*)d_in[4];
    const int*   esrc  = (const int*)d_in[5];
    const int*   edst  = (const int*)d_in[6];
    float* out = (float*)d_out;

    const int initBlocks = (NN * DD / 4 + 255) / 256;
    k_init<<<initBlocks, 256>>>();
    k_deg<<<(NE + 255) / 256, 256>>>(edst);
    k_prep<<<(NN + 255) / 256, 256>>>(W);
    k_scatter<<<(NE * 8 + 255) / 256, 256>>>(feat, esrc, edst);
    k_gemm<<<(NN + 31) / 32, 256>>>(b);
    k_finalize<<<1, DD>>>(gamma, beta);
    k_epilogue<<<initBlocks, 256>>>(feat, out);
}